// round 5
// baseline (speedup 1.0000x reference)
#include <cuda_runtime.h>
#include <cstdint>

#define BATCH 64
#define NSTEPS 2000
#define TAPS 64
#define NTHREADS 128
#define SYM_PERIOD 100
#define CHUNK 16
#define NCHUNK (NSTEPS / CHUNK)   // 125
#define BPC 2                     // batches per CTA
#define NCTA (BATCH / BPC)        // 32

__device__ __forceinline__ void cp16(uint32_t dst_smem, const void* src_gmem) {
    asm volatile("cp.async.cg.shared.global [%0], [%1], 16;\n"
                 :: "r"(dst_smem), "l"(src_gmem));
}
__device__ __forceinline__ void cp_commit() {
    asm volatile("cp.async.commit_group;\n");
}
template <int N>
__device__ __forceinline__ void cp_wait() {
    asm volatile("cp.async.wait_group %0;\n" :: "n"(N));
}

__global__ void __launch_bounds__(NTHREADS, 1)
rls_kernel(const float* __restrict__ x_seq,
           const float* __restrict__ d_seq,
           const float* __restrict__ lambdas,
           float* __restrict__ y_out,
           float* __restrict__ w_out)
{
    const int tid  = threadIdx.x;
    const int i    = tid >> 1;   // row 0..63
    const int c    = tid & 1;    // column-half 0/1
    const int lane = tid & 31;
    const int warp = tid >> 5;

    __shared__ __align__(16) float xc[BPC][2][CHUNK][TAPS];  // 16 KB
    __shared__ __align__(16) float dc[BPC][2][CHUNK];
    __shared__ __align__(16) float lc[2][CHUNK];
    __shared__ __align__(16) float Uxbuf[2][BPC][TAPS];
    __shared__ float red[2][BPC][4][2];
    __shared__ float tile[TAPS][TAPS + 1];                   // 16.25 KB

    // Q row-half in registers per batch: row i, cols [32c,32c+32). P = sigma*Q.
    float Q[BPC][32];
#pragma unroll
    for (int bp = 0; bp < BPC; bp++) {
#pragma unroll
        for (int j = 0; j < 32; j++) Q[bp][j] = 0.0f;
        if ((i >> 5) == c) Q[bp][i & 31] = 1.0f;
    }
    float w[BPC] = {0.0f, 0.0f};
    float sigma = 1.0f;          // identical across batches (lambda is global)

    const int b0 = blockIdx.x * BPC;
    const float* xb[BPC];
    const float* db[BPC];
#pragma unroll
    for (int bp = 0; bp < BPC; bp++) {
        xb[bp] = x_seq + (size_t)(b0 + bp) * NSTEPS * TAPS;
        db[bp] = d_seq + (size_t)(b0 + bp) * NSTEPS;
    }

    const uint32_t xc_s = (uint32_t)__cvta_generic_to_shared(&xc[0][0][0][0]);
    const uint32_t dc_s = (uint32_t)__cvta_generic_to_shared(&dc[0][0][0]);
    const uint32_t lc_s = (uint32_t)__cvta_generic_to_shared(&lc[0][0]);

    auto issue_chunk = [&](int ck, int cb) {
#pragma unroll
        for (int bp = 0; bp < BPC; bp++)
#pragma unroll
            for (int j = 0; j < 2; j++)   // 4 KB x per batch-chunk
                cp16(xc_s + ((bp * 2 + cb) * (CHUNK * TAPS) + j * 512) * 4 + tid * 16,
                     xb[bp] + (size_t)ck * CHUNK * TAPS + j * 512 + tid * 4);
        if (tid < 4)
            cp16(dc_s + ((0 * 2 + cb) * CHUNK) * 4 + tid * 16,
                 db[0] + ck * CHUNK + tid * 4);
        else if (tid < 8)
            cp16(dc_s + ((1 * 2 + cb) * CHUNK) * 4 + (tid - 4) * 16,
                 db[1] + ck * CHUNK + (tid - 4) * 4);
        else if (tid < 12)
            cp16(lc_s + (cb * CHUNK) * 4 + (tid - 8) * 16,
                 lambdas + ck * CHUNK + (tid - 8) * 4);
        cp_commit();
    };

    issue_chunk(0, 0);
    issue_chunk(1, 1);
    cp_wait<1>();
    __syncthreads();

    for (int t = 0; t < NSTEPS; t++) {
        const int s  = t & (CHUNK - 1);
        const int ck = t >> 4;
        const int cb = ck & 1;
        const int pb = t & 1;

        if (s == 0 && t > 0) {
            if (ck + 1 < NCHUNK) { issue_chunk(ck + 1, cb ^ 1); cp_wait<1>(); }
            else                 { cp_wait<0>(); }
            __syncthreads();
        }

        const float lam_r = lc[cb][s];
        float d_r[BPC];
#pragma unroll
        for (int bp = 0; bp < BPC; bp++) d_r[bp] = dc[bp][cb][s];

        // ---- u = Q x : both batches interleaved ----
        float pxp[BPC];
#pragma unroll
        for (int bp = 0; bp < BPC; bp++) {
            const float4* xs = (const float4*)(&xc[bp][cb][s][c * 32]);
            float a0 = 0.f, a1 = 0.f, a2 = 0.f, a3 = 0.f;
#pragma unroll
            for (int k = 0; k < 8; k++) {
                const float4 q = xs[k];
                a0 = fmaf(Q[bp][4 * k + 0], q.x, a0);
                a1 = fmaf(Q[bp][4 * k + 1], q.y, a1);
                a2 = fmaf(Q[bp][4 * k + 2], q.z, a2);
                a3 = fmaf(Q[bp][4 * k + 3], q.w, a3);
            }
            pxp[bp] = (a0 + a1) + (a2 + a3);
        }
        float Uxi[BPC], s1[BPC], s2[BPC];
#pragma unroll
        for (int bp = 0; bp < BPC; bp++)
            Uxi[bp] = pxp[bp] + __shfl_xor_sync(0xffffffffu, pxp[bp], 1);
#pragma unroll
        for (int bp = 0; bp < BPC; bp++) {
            const float xi = xc[bp][cb][s][i];
            s1[bp] = xi * pxp[bp];
            s2[bp] = (c == 0) ? w[bp] * xi : 0.0f;
        }
#pragma unroll
        for (int off = 16; off >= 1; off >>= 1) {
#pragma unroll
            for (int bp = 0; bp < BPC; bp++) {
                s1[bp] += __shfl_xor_sync(0xffffffffu, s1[bp], off);
                s2[bp] += __shfl_xor_sync(0xffffffffu, s2[bp], off);
            }
        }
        if (lane == 0) {
#pragma unroll
            for (int bp = 0; bp < BPC; bp++) {
                red[pb][bp][warp][0] = s1[bp];
                red[pb][bp][warp][1] = s2[bp];
            }
        }
        if (c == 0) {
#pragma unroll
            for (int bp = 0; bp < BPC; bp++) Uxbuf[pb][bp][i] = Uxi[bp];
        }

        __syncthreads();   // the one mandatory barrier per step

        const float lam  = fminf(fmaxf(lam_r, 1e-4f), 0.9999f);
        const float rlam = 1.0f / lam;
#pragma unroll
        for (int bp = 0; bp < BPC; bp++) {
            const float s1t  = (red[pb][bp][0][0] + red[pb][bp][1][0]) +
                               (red[pb][bp][2][0] + red[pb][bp][3][0]);
            const float yhat = (red[pb][bp][0][1] + red[pb][bp][1][1]) +
                               (red[pb][bp][2][1] + red[pb][bp][3][1]);
            const float denom = fmaf(sigma, s1t, lam);
            const float kk    = sigma * __fdividef(1.0f, denom);
            const float e     = d_r[bp] - yhat;
            w[bp] = fmaf(kk * e, Uxi[bp], w[bp]);
            if (tid == bp) y_out[(size_t)(b0 + bp) * NSTEPS + t] = yhat;

            // Q -= kk * u u'
            const float m = -kk * Uxi[bp];
            const float4* us = (const float4*)(&Uxbuf[pb][bp][c * 32]);
#pragma unroll
            for (int k = 0; k < 8; k++) {
                const float4 q = us[k];
                Q[bp][4 * k + 0] = fmaf(m, q.x, Q[bp][4 * k + 0]);
                Q[bp][4 * k + 1] = fmaf(m, q.y, Q[bp][4 * k + 1]);
                Q[bp][4 * k + 2] = fmaf(m, q.z, Q[bp][4 * k + 2]);
                Q[bp][4 * k + 3] = fmaf(m, q.w, Q[bp][4 * k + 3]);
            }
        }
        sigma *= rlam;

        // ---- periodic symmetrization (kills undamped antisym mode) ----
        if ((t % SYM_PERIOD) == (SYM_PERIOD - 1)) {
#pragma unroll
            for (int bp = 0; bp < BPC; bp++) {
#pragma unroll
                for (int j = 0; j < 32; j++) tile[i][32 * c + j] = Q[bp][j];
                __syncthreads();
#pragma unroll
                for (int j = 0; j < 32; j++)
                    Q[bp][j] = 0.5f * (Q[bp][j] + tile[32 * c + j][i]);
                __syncthreads();
            }
        }
    }

    if (c == 0) {
#pragma unroll
        for (int bp = 0; bp < BPC; bp++)
            w_out[(size_t)(b0 + bp) * TAPS + i] = w[bp];
    }
}

extern "C" void kernel_launch(void* const* d_in, const int* in_sizes, int n_in,
                              void* d_out, int out_size)
{
    const float* x_seq   = (const float*)d_in[0];
    const float* d_seq   = (const float*)d_in[1];
    const float* lambdas = (const float*)d_in[2];
    float* y_out = (float*)d_out;                          // [64, 2000]
    float* w_out = (float*)d_out + (size_t)BATCH * NSTEPS; // [64, 64]
    rls_kernel<<<NCTA, NTHREADS>>>(x_seq, d_seq, lambdas, y_out, w_out);
}

// round 6
// speedup vs baseline: 1.0228x; 1.0228x over previous
#include <cuda_runtime.h>
#include <cstdint>

#define BATCH 64
#define NSTEPS 2000
#define TAPS 64
#define SYM_PERIOD 100
#define CHUNK 16
#define NCHUNK (NSTEPS / CHUNK)   // 125
#define GROUPS 2                  // independent batches per CTA (decoupled warp-groups)
#define GTHREADS 128
#define NTHREADS (GROUPS * GTHREADS)
#define NCTA (BATCH / GROUPS)     // 32

__device__ __forceinline__ void cp16(uint32_t dst_smem, const void* src_gmem) {
    asm volatile("cp.async.cg.shared.global [%0], [%1], 16;\n"
                 :: "r"(dst_smem), "l"(src_gmem));
}
__device__ __forceinline__ void cp_commit() {
    asm volatile("cp.async.commit_group;\n");
}
template <int N>
__device__ __forceinline__ void cp_wait() {
    asm volatile("cp.async.wait_group %0;\n" :: "n"(N));
}
__device__ __forceinline__ void gbar(int g) {   // per-group named barrier
    asm volatile("bar.sync %0, %1;" :: "r"(g + 1), "r"(GTHREADS) : "memory");
}

__global__ void __launch_bounds__(NTHREADS, 1)
rls_kernel(const float* __restrict__ x_seq,
           const float* __restrict__ d_seq,
           const float* __restrict__ lambdas,
           float* __restrict__ y_out,
           float* __restrict__ w_out)
{
    const int tid  = threadIdx.x;
    const int g    = tid >> 7;        // group 0/1
    const int gtid = tid & (GTHREADS - 1);
    const int i    = gtid >> 1;       // row 0..63
    const int c    = gtid & 1;        // column-half 0/1
    const int lane = gtid & 31;
    const int warp = gtid >> 5;       // warp within group

    __shared__ __align__(16) float xc[GROUPS][2][CHUNK][TAPS];  // 16 KB
    __shared__ __align__(16) float dc[GROUPS][2][CHUNK];
    __shared__ __align__(16) float lc[GROUPS][2][CHUNK];
    __shared__ __align__(16) float Uxbuf[GROUPS][2][TAPS];
    __shared__ float red[GROUPS][2][4][2];
    __shared__ float tile[TAPS][TAPS + 1];     // shared transpose scratch (serialized)

    // Q row-half in registers: row i, cols [32c, 32c+32).  P = sigma * Q.
    float Q[32];
#pragma unroll
    for (int j = 0; j < 32; j++) Q[j] = 0.0f;
    if ((i >> 5) == c) Q[i & 31] = 1.0f;
    float w = 0.0f;
    float sigma = 1.0f;

    const int b = blockIdx.x * GROUPS + g;
    const float* xb = x_seq + (size_t)b * NSTEPS * TAPS;
    const float* db = d_seq + (size_t)b * NSTEPS;

    const uint32_t xc_s = (uint32_t)__cvta_generic_to_shared(&xc[g][0][0][0]);
    const uint32_t dc_s = (uint32_t)__cvta_generic_to_shared(&dc[g][0][0]);
    const uint32_t lc_s = (uint32_t)__cvta_generic_to_shared(&lc[g][0][0]);

    auto issue_chunk = [&](int ck, int cb) {
#pragma unroll
        for (int j = 0; j < 2; j++)   // 4 KB of x per chunk = 2 x 16B per thread
            cp16(xc_s + (uint32_t)(cb * (CHUNK * TAPS) + j * 512) * 4 + gtid * 16,
                 xb + (size_t)ck * CHUNK * TAPS + j * 512 + gtid * 4);
        if (gtid < 4)
            cp16(dc_s + (uint32_t)(cb * CHUNK) * 4 + gtid * 16,
                 db + ck * CHUNK + gtid * 4);
        else if (gtid < 8)
            cp16(lc_s + (uint32_t)(cb * CHUNK) * 4 + (gtid - 4) * 16,
                 lambdas + ck * CHUNK + (gtid - 4) * 4);
        cp_commit();
    };

    issue_chunk(0, 0);
    issue_chunk(1, 1);
    cp_wait<1>();
    gbar(g);

    for (int t = 0; t < NSTEPS; t++) {
        const int s  = t & (CHUNK - 1);
        const int ck = t >> 4;
        const int cb = ck & 1;
        const int pb = t & 1;

        if (s == 0 && t > 0) {
            if (ck + 1 < NCHUNK) { issue_chunk(ck + 1, cb ^ 1); cp_wait<1>(); }
            else                 { cp_wait<0>(); }
            gbar(g);
        }

        const float d_r   = dc[g][cb][s];
        const float lam_r = lc[g][cb][s];

        // ---- u = Q x  (thread's 32-col partial) ----
        const float4* xs = (const float4*)(&xc[g][cb][s][c * 32]);
        float a0 = 0.f, a1 = 0.f, a2 = 0.f, a3 = 0.f;
#pragma unroll
        for (int k = 0; k < 8; k++) {
            const float4 q = xs[k];
            a0 = fmaf(Q[4 * k + 0], q.x, a0);
            a1 = fmaf(Q[4 * k + 1], q.y, a1);
            a2 = fmaf(Q[4 * k + 2], q.z, a2);
            a3 = fmaf(Q[4 * k + 3], q.w, a3);
        }
        const float pxp = (a0 + a1) + (a2 + a3);
        const float Uxi = pxp + __shfl_xor_sync(0xffffffffu, pxp, 1);

        const float xi = xc[g][cb][s][i];
        float s1 = xi * pxp;                    // -> x . u
        float s2 = (c == 0) ? w * xi : 0.0f;    // -> y_hat
#pragma unroll
        for (int off = 16; off >= 1; off >>= 1) {
            s1 += __shfl_xor_sync(0xffffffffu, s1, off);
            s2 += __shfl_xor_sync(0xffffffffu, s2, off);
        }
        if (lane == 0) { red[g][pb][warp][0] = s1; red[g][pb][warp][1] = s2; }
        if (c == 0)    Uxbuf[g][pb][i] = Uxi;

        gbar(g);   // the one per-step barrier (group-local: no cross-group lockstep)

        // ---- scalar stage (redundant on all group threads) ----
        const float lam  = fminf(fmaxf(lam_r, 1e-4f), 0.9999f);
        const float s1t  = (red[g][pb][0][0] + red[g][pb][1][0]) +
                           (red[g][pb][2][0] + red[g][pb][3][0]);
        const float yhat = (red[g][pb][0][1] + red[g][pb][1][1]) +
                           (red[g][pb][2][1] + red[g][pb][3][1]);
        const float denom = fmaf(sigma, s1t, lam);
        const float kk    = sigma * __fdividef(1.0f, denom);
        const float e     = d_r - yhat;
        w = fmaf(kk * e, Uxi, w);
        if (gtid == 0) y_out[(size_t)b * NSTEPS + t] = yhat;
        sigma = sigma / lam;     // exact div: sigma error never damps

        // ---- Q rank-1 update: Q -= kk * u u'  ----
        const float m = -kk * Uxi;
        const float4* us = (const float4*)(&Uxbuf[g][pb][c * 32]);
#pragma unroll
        for (int k = 0; k < 8; k++) {
            const float4 q = us[k];
            Q[4 * k + 0] = fmaf(m, q.x, Q[4 * k + 0]);
            Q[4 * k + 1] = fmaf(m, q.y, Q[4 * k + 1]);
            Q[4 * k + 2] = fmaf(m, q.z, Q[4 * k + 2]);
            Q[4 * k + 3] = fmaf(m, q.w, Q[4 * k + 3]);
        }

        // ---- periodic symmetrization (kills the undamped antisym mode).
        //      Groups serialize through one shared tile; rare (every 100). ----
        if ((t % SYM_PERIOD) == (SYM_PERIOD - 1)) {
            __syncthreads();
            if (g == 0) {
#pragma unroll
                for (int j = 0; j < 32; j++) tile[i][32 * c + j] = Q[j];
            }
            __syncthreads();
            if (g == 0) {
#pragma unroll
                for (int j = 0; j < 32; j++)
                    Q[j] = 0.5f * (Q[j] + tile[32 * c + j][i]);
            }
            __syncthreads();
            if (g == 1) {
#pragma unroll
                for (int j = 0; j < 32; j++) tile[i][32 * c + j] = Q[j];
            }
            __syncthreads();
            if (g == 1) {
#pragma unroll
                for (int j = 0; j < 32; j++)
                    Q[j] = 0.5f * (Q[j] + tile[32 * c + j][i]);
            }
            __syncthreads();
        }
    }

    if (c == 0) w_out[(size_t)b * TAPS + i] = w;
}

extern "C" void kernel_launch(void* const* d_in, const int* in_sizes, int n_in,
                              void* d_out, int out_size)
{
    const float* x_seq   = (const float*)d_in[0];
    const float* d_seq   = (const float*)d_in[1];
    const float* lambdas = (const float*)d_in[2];
    float* y_out = (float*)d_out;                          // [64, 2000]
    float* w_out = (float*)d_out + (size_t)BATCH * NSTEPS; // [64, 64]
    rls_kernel<<<NCTA, NTHREADS>>>(x_seq, d_seq, lambdas, y_out, w_out);
}

// round 7
// speedup vs baseline: 1.7662x; 1.7269x over previous
#include <cuda_runtime.h>
#include <cstdint>

#define BATCH 64
#define NSTEPS 2000
#define TAPS 64
#define NTHREADS 128
#define SYM_PERIOD 100
#define CHUNK 16
#define NCHUNK (NSTEPS / CHUNK)   // 125

__device__ __forceinline__ void cp16(uint32_t dst_smem, const void* src_gmem) {
    asm volatile("cp.async.cg.shared.global [%0], [%1], 16;\n"
                 :: "r"(dst_smem), "l"(src_gmem));
}
__device__ __forceinline__ void cp_commit() {
    asm volatile("cp.async.commit_group;\n");
}
template <int N>
__device__ __forceinline__ void cp_wait() {
    asm volatile("cp.async.wait_group %0;\n" :: "n"(N));
}

__global__ void __launch_bounds__(NTHREADS, 1)
rls_kernel(const float* __restrict__ x_seq,
           const float* __restrict__ d_seq,
           const float* __restrict__ lambdas,
           float* __restrict__ y_out,
           float* __restrict__ w_out)
{
    const int b    = blockIdx.x;
    const int tid  = threadIdx.x;
    const int i    = tid >> 1;   // row 0..63
    const int c    = tid & 1;    // column-half 0/1
    const int lane = tid & 31;
    const int warp = tid >> 5;

    __shared__ __align__(16) float xc[4][CHUNK][TAPS];   // 16 KB, 4 rotating chunk bufs
    __shared__ __align__(16) float dc[4][CHUNK];
    __shared__ __align__(16) float lc[4][CHUNK];
    __shared__ __align__(16) float Uxbuf[2][TAPS];
    __shared__ float red[2][4][4];                        // beta, gamma, delta
    __shared__ float tile[TAPS][TAPS + 1];                // transpose scratch

    // Q row-half in registers: row i, cols [32c, 32c+32).  P = sigma * Q.
    float Q[32];
#pragma unroll
    for (int j = 0; j < 32; j++) Q[j] = 0.0f;
    if ((i >> 5) == c) Q[i & 31] = 1.0f;
    float w = 0.0f;
    float sigma = 1.0f;

    const float* xb = x_seq + (size_t)b * NSTEPS * TAPS;
    const float* db = d_seq + (size_t)b * NSTEPS;

    const uint32_t xc_s = (uint32_t)__cvta_generic_to_shared(&xc[0][0][0]);
    const uint32_t dc_s = (uint32_t)__cvta_generic_to_shared(&dc[0][0]);
    const uint32_t lc_s = (uint32_t)__cvta_generic_to_shared(&lc[0][0]);

    auto issue_chunk = [&](int ck, int cb) {
#pragma unroll
        for (int j = 0; j < 2; j++)   // 4 KB of x per chunk
            cp16(xc_s + (uint32_t)(cb * (CHUNK * TAPS) + j * 512) * 4 + tid * 16,
                 xb + (size_t)ck * CHUNK * TAPS + j * 512 + tid * 4);
        if (tid < 4)
            cp16(dc_s + (uint32_t)(cb * CHUNK) * 4 + tid * 16,
                 db + ck * CHUNK + tid * 4);
        else if (tid < 8)
            cp16(lc_s + (uint32_t)(cb * CHUNK) * 4 + (tid - 4) * 16,
                 lambdas + ck * CHUNK + (tid - 4) * 4);
        cp_commit();
    };

    // prologue: chunks 0,1 in flight; wait for chunk 0
    issue_chunk(0, 0);
    issue_chunk(1, 1);
    cp_wait<1>();
    __syncthreads();

    // ---- bootstrap: u_0 = x_0 (Q=I), alpha_0 = x_0'x_0, y_0 = 0 ----
    const float x0i = xc[0][0][i];
    float Uxi = x0i;                       // u_t,i  (this thread's row)
    if (c == 0) Uxbuf[0][i] = x0i;
    float ap = (c == 0) ? x0i * x0i : 0.0f;
#pragma unroll
    for (int off = 16; off >= 1; off >>= 1)
        ap += __shfl_xor_sync(0xffffffffu, ap, off);
    if (lane == 0) red[1][warp][0] = ap;   // use pb=1 slot (iter 0 uses pb=0)
    __syncthreads();
    float alpha = (red[1][0][0] + red[1][1][0]) + (red[1][2][0] + red[1][3][0]);
    float y = 0.0f;

    for (int t = 0; t < NSTEPS; t++) {
        const int s  = t & (CHUNK - 1);
        const int ck = t >> 4;
        const int pb = t & 1;      // red ping-pong
        const int ub = t & 1;      // Uxbuf: read [ub] (u_t), write [ub^1] (u_{t+1})

        if (s == 0) {
            // keep chunks ck, ck+1 resident; stream in ck+2
            if (ck + 2 < NCHUNK) { issue_chunk(ck + 2, (ck + 2) & 3); cp_wait<1>(); }
            else                 { cp_wait<0>(); }
            __syncthreads();
        }

        const int t1  = (t + 1 < NSTEPS) ? t + 1 : t;   // clamped lookahead
        const int cb1 = (t1 >> 4) & 3;
        const int sl1 = t1 & (CHUNK - 1);
        const int cbt = ck & 3;

        // ---- step-t scalars (alpha, y carried in regs from last iter) ----
        const float d_r   = dc[cbt][s];
        const float lam_r = lc[cbt][s];
        const float lam   = fminf(fmaxf(lam_r, 1e-4f), 0.9999f);
        const float denom = fmaf(sigma, alpha, lam);
        const float kk    = sigma * __fdividef(1.0f, denom);
        const float e     = d_r - y;
        if (tid == 0) y_out[(size_t)b * NSTEPS + t] = y;
        w = fmaf(kk * e, Uxi, w);            // w_{t+1}
        sigma = sigma / lam;                  // exact: sigma error never damps

        // ---- lookahead matvec v = Q_t x_{t+1} ----
        const float4* xs = (const float4*)(&xc[cb1][sl1][c * 32]);
        float a0 = 0.f, a1 = 0.f, a2 = 0.f, a3 = 0.f;
#pragma unroll
        for (int k = 0; k < 8; k++) {
            const float4 q = xs[k];
            a0 = fmaf(Q[4 * k + 0], q.x, a0);
            a1 = fmaf(Q[4 * k + 1], q.y, a1);
            a2 = fmaf(Q[4 * k + 2], q.z, a2);
            a3 = fmaf(Q[4 * k + 3], q.w, a3);
        }
        const float vpart = (a0 + a1) + (a2 + a3);
        const float Vxi   = vpart + __shfl_xor_sync(0xffffffffu, vpart, 1);

        // ---- lookahead reductions: beta = x1'v, gamma = u'x1, delta = w_{t+1}'x1 ----
        const float x1i = xc[cb1][sl1][i];
        float bp = x1i * vpart;
        float gp = (c == 0) ? Uxi * x1i : 0.0f;
        float dp = (c == 0) ? w * x1i : 0.0f;
#pragma unroll
        for (int off = 16; off >= 1; off >>= 1) {
            bp += __shfl_xor_sync(0xffffffffu, bp, off);
            gp += __shfl_xor_sync(0xffffffffu, gp, off);
            dp += __shfl_xor_sync(0xffffffffu, dp, off);
        }
        if (lane == 0) {
            red[pb][warp][0] = bp;
            red[pb][warp][1] = gp;
            red[pb][warp][2] = dp;
        }

        __syncthreads();   // the one per-step barrier

        // ---- combine & pipeline carry for step t+1 ----
        const float beta = (red[pb][0][0] + red[pb][1][0]) +
                           (red[pb][2][0] + red[pb][3][0]);
        const float gam  = (red[pb][0][1] + red[pb][1][1]) +
                           (red[pb][2][1] + red[pb][3][1]);
        y                = (red[pb][0][2] + red[pb][1][2]) +
                           (red[pb][2][2] + red[pb][3][2]);   // y_{t+1}
        const float kg = kk * gam;
        alpha = fmaf(-kg, gam, beta);                          // alpha_{t+1}
        const float unew = fmaf(-kg, Uxi, Vxi);                // u_{t+1},i

        // ---- Q_{t+1} = Q_t - kk * u_t u_t'  (reads u_t vector from smem) ----
        const float m = -kk * Uxi;
        const float4* us = (const float4*)(&Uxbuf[ub][c * 32]);
#pragma unroll
        for (int k = 0; k < 8; k++) {
            const float4 q = us[k];
            Q[4 * k + 0] = fmaf(m, q.x, Q[4 * k + 0]);
            Q[4 * k + 1] = fmaf(m, q.y, Q[4 * k + 1]);
            Q[4 * k + 2] = fmaf(m, q.z, Q[4 * k + 2]);
            Q[4 * k + 3] = fmaf(m, q.w, Q[4 * k + 3]);
        }
        if (c == 0) Uxbuf[ub ^ 1][i] = unew;
        Uxi = unew;

        // ---- periodic symmetrization (kills the undamped antisym mode) ----
        if ((t % SYM_PERIOD) == (SYM_PERIOD - 1)) {
#pragma unroll
            for (int j = 0; j < 32; j++) tile[i][32 * c + j] = Q[j];
            __syncthreads();
#pragma unroll
            for (int j = 0; j < 32; j++)
                Q[j] = 0.5f * (Q[j] + tile[32 * c + j][i]);
            __syncthreads();
        }
    }

    if (c == 0) w_out[(size_t)b * TAPS + i] = w;
}

extern "C" void kernel_launch(void* const* d_in, const int* in_sizes, int n_in,
                              void* d_out, int out_size)
{
    const float* x_seq   = (const float*)d_in[0];
    const float* d_seq   = (const float*)d_in[1];
    const float* lambdas = (const float*)d_in[2];
    float* y_out = (float*)d_out;                          // [64, 2000]
    float* w_out = (float*)d_out + (size_t)BATCH * NSTEPS; // [64, 64]
    rls_kernel<<<BATCH, NTHREADS>>>(x_seq, d_seq, lambdas, y_out, w_out);
}

// round 9
// speedup vs baseline: 1.7872x; 1.0119x over previous
#include <cuda_runtime.h>
#include <cstdint>

#define BATCH 64
#define NSTEPS 2000
#define TAPS 64
#define NTHREADS 128
#define CHUNK 16
#define NCHUNK (NSTEPS / CHUNK)   // 125
#define SYM_CHUNKS 6              // symmetrize every 96 steps

__device__ __forceinline__ void cp16(uint32_t dst_smem, const void* src_gmem) {
    asm volatile("cp.async.cg.shared.global [%0], [%1], 16;\n"
                 :: "r"(dst_smem), "l"(src_gmem));
}
__device__ __forceinline__ void cp_commit() {
    asm volatile("cp.async.commit_group;\n");
}
template <int N>
__device__ __forceinline__ void cp_wait() {
    asm volatile("cp.async.wait_group %0;\n" :: "n"(N));
}

__global__ void __launch_bounds__(NTHREADS, 1)
rls_kernel(const float* __restrict__ x_seq,
           const float* __restrict__ d_seq,
           const float* __restrict__ lambdas,
           float* __restrict__ y_out,
           float* __restrict__ w_out)
{
    const int b    = blockIdx.x;
    const int tid  = threadIdx.x;
    const int i    = tid >> 1;   // row 0..63
    const int c    = tid & 1;    // column-half 0/1
    const int lane = tid & 31;
    const int warp = tid >> 5;

    __shared__ __align__(16) float xc[4][CHUNK][TAPS];   // 16 KB rotating chunk bufs
    __shared__ __align__(16) float dc[4][CHUNK];
    __shared__ __align__(16) float lc[4][CHUNK];
    __shared__ __align__(16) float Uxbuf[2][TAPS];
    __shared__ __align__(16) float  redb[2][4][4];       // beta partials (4/warp)
    __shared__ __align__(16) float2 redgd[2][4];         // {gamma_w, delta_w}
    __shared__ float tile[TAPS][TAPS + 1];               // transpose scratch

    float Q[32];                 // row i, cols [32c,32c+32). P = sigma * Q.
#pragma unroll
    for (int j = 0; j < 32; j++) Q[j] = 0.0f;
    if ((i >> 5) == c) Q[i & 31] = 1.0f;
    float w = 0.0f;
    float sigma = 1.0f;

    const float* xb = x_seq + (size_t)b * NSTEPS * TAPS;
    const float* db = d_seq + (size_t)b * NSTEPS;

    const uint32_t xc_s = (uint32_t)__cvta_generic_to_shared(&xc[0][0][0]);
    const uint32_t dc_s = (uint32_t)__cvta_generic_to_shared(&dc[0][0]);
    const uint32_t lc_s = (uint32_t)__cvta_generic_to_shared(&lc[0][0]);

    auto issue_chunk = [&](int ck, int cb) {
#pragma unroll
        for (int j = 0; j < 2; j++)
            cp16(xc_s + (uint32_t)(cb * (CHUNK * TAPS) + j * 512) * 4 + tid * 16,
                 xb + (size_t)ck * CHUNK * TAPS + j * 512 + tid * 4);
        if (tid < 4)
            cp16(dc_s + (uint32_t)(cb * CHUNK) * 4 + tid * 16,
                 db + ck * CHUNK + tid * 4);
        else if (tid < 8)
            cp16(lc_s + (uint32_t)(cb * CHUNK) * 4 + (tid - 4) * 16,
                 lambdas + ck * CHUNK + (tid - 4) * 4);
        cp_commit();
    };

    issue_chunk(0, 0);
    issue_chunk(1, 1);
    cp_wait<1>();
    __syncthreads();

    // ---- bootstrap: u_0 = x_0 (Q=I), alpha_0 = x_0'x_0, y_0 = 0 ----
    const float x0i = xc[0][0][i];
    float Uxi = x0i;
    if (c == 0) Uxbuf[0][i] = x0i;
    float ap = (c == 0) ? x0i * x0i : 0.0f;
#pragma unroll
    for (int off = 16; off >= 2; off >>= 1)
        ap += __shfl_xor_sync(0xffffffffu, ap, off);
    if (lane == 0) redgd[1][warp].x = ap;
    __syncthreads();
    float alpha = (redgd[1][0].x + redgd[1][1].x) +
                  (redgd[1][2].x + redgd[1][3].x);
    float y = 0.0f;

    for (int ck = 0; ck < NCHUNK; ck++) {
        if (ck + 2 < NCHUNK) { issue_chunk(ck + 2, (ck + 2) & 3); cp_wait<1>(); }
        else                 { cp_wait<0>(); }
        __syncthreads();

        const int cbt = ck & 3;
        const int tb  = ck * CHUNK;

#pragma unroll 4
        for (int s = 0; s < CHUNK; s++) {
            const int t  = tb + s;
            const int pb = t & 1;
            const int ub = t & 1;

            // ---- step-t scalars (alpha, y carried in regs) ----
            const float d_r   = dc[cbt][s];
            const float lam_r = lc[cbt][s];
            const float lam   = fminf(fmaxf(lam_r, 1e-4f), 0.9999f);
            const float denom = fmaf(sigma, alpha, lam);
            const float kk    = sigma * __fdividef(1.0f, denom);
            const float e     = d_r - y;
            if (tid == 0) y_out[(size_t)b * NSTEPS + t] = y;
            w = fmaf(kk * e, Uxi, w);            // w_{t+1}
            sigma = sigma / lam;                  // exact div (error never damps)

            // ---- lookahead x_{t+1} (clamped at the end) ----
            const int t1 = (t + 1 < NSTEPS) ? t + 1 : t;
            const float* x1 = &xc[(t1 >> 4) & 3][t1 & (CHUNK - 1)][0];
            const float x1i = x1[i];

            // ---- merged gamma/delta parity tree (issued BEFORE matvec so its
            //      shuffle latency hides under the FMA stream) ----
            float md = (c == 0) ? Uxi * x1i : w * x1i;
#pragma unroll
            for (int off = 16; off >= 2; off >>= 1)
                md += __shfl_xor_sync(0xffffffffu, md, off);
            if (lane == 0) redgd[pb][warp].x = md;   // gamma_w (even lanes)
            if (lane == 1) redgd[pb][warp].y = md;   // delta_w (odd lanes)

            // ---- matvec v = Q_t x_{t+1} ----
            const float4* xs = (const float4*)(x1 + c * 32);
            float a0 = 0.f, a1 = 0.f, a2 = 0.f, a3 = 0.f;
#pragma unroll
            for (int k = 0; k < 8; k++) {
                const float4 q = xs[k];
                a0 = fmaf(Q[4 * k + 0], q.x, a0);
                a1 = fmaf(Q[4 * k + 1], q.y, a1);
                a2 = fmaf(Q[4 * k + 2], q.z, a2);
                a3 = fmaf(Q[4 * k + 3], q.w, a3);
            }
            const float vpart = (a0 + a1) + (a2 + a3);
            const float Vxi   = vpart + __shfl_xor_sync(0xffffffffu, vpart, 1);

            // ---- beta partials: 3-level tree, finish post-barrier ----
            float bp = x1i * vpart;
            bp += __shfl_xor_sync(0xffffffffu, bp, 16);
            bp += __shfl_xor_sync(0xffffffffu, bp, 8);
            bp += __shfl_xor_sync(0xffffffffu, bp, 4);
            if (lane < 4) redb[pb][warp][lane] = bp;

            __syncthreads();   // the one per-step barrier

            // ---- combine & pipeline carry for t+1 ----
            const float4 b0 = *(const float4*)redb[pb][0];
            const float4 b1 = *(const float4*)redb[pb][1];
            const float4 b2 = *(const float4*)redb[pb][2];
            const float4 b3 = *(const float4*)redb[pb][3];
            const float beta = ((b0.x + b0.y) + (b0.z + b0.w))
                             + ((b1.x + b1.y) + (b1.z + b1.w))
                             + ((b2.x + b2.y) + (b2.z + b2.w))
                             + ((b3.x + b3.y) + (b3.z + b3.w));
            const float2 g0 = redgd[pb][0], g1 = redgd[pb][1],
                         g2 = redgd[pb][2], g3 = redgd[pb][3];
            const float gam = (g0.x + g1.x) + (g2.x + g3.x);
            y               = (g0.y + g1.y) + (g2.y + g3.y);   // y_{t+1}
            const float kg = kk * gam;
            alpha = fmaf(-kg, gam, beta);                       // alpha_{t+1}
            const float unew = fmaf(-kg, Uxi, Vxi);             // u_{t+1},i

            // ---- Q_{t+1} = Q_t - kk * u_t u_t' ----
            const float m = -kk * Uxi;
            const float4* us = (const float4*)(&Uxbuf[ub][c * 32]);
#pragma unroll
            for (int k = 0; k < 8; k++) {
                const float4 q = us[k];
                Q[4 * k + 0] = fmaf(m, q.x, Q[4 * k + 0]);
                Q[4 * k + 1] = fmaf(m, q.y, Q[4 * k + 1]);
                Q[4 * k + 2] = fmaf(m, q.z, Q[4 * k + 2]);
                Q[4 * k + 3] = fmaf(m, q.w, Q[4 * k + 3]);
            }
            if (c == 0) Uxbuf[ub ^ 1][i] = unew;
            Uxi = unew;
        }

        // ---- symmetrize every SYM_CHUNKS chunks (kills undamped antisym mode) ----
        if ((ck % SYM_CHUNKS) == (SYM_CHUNKS - 1)) {
#pragma unroll
            for (int j = 0; j < 32; j++) tile[i][32 * c + j] = Q[j];
            __syncthreads();
#pragma unroll
            for (int j = 0; j < 32; j++)
                Q[j] = 0.5f * (Q[j] + tile[32 * c + j][i]);
            __syncthreads();
        }
    }

    if (c == 0) w_out[(size_t)b * TAPS + i] = w;
}

extern "C" void kernel_launch(void* const* d_in, const int* in_sizes, int n_in,
                              void* d_out, int out_size)
{
    const float* x_seq   = (const float*)d_in[0];
    const float* d_seq   = (const float*)d_in[1];
    const float* lambdas = (const float*)d_in[2];
    float* y_out = (float*)d_out;                          // [64, 2000]
    float* w_out = (float*)d_out + (size_t)BATCH * NSTEPS; // [64, 64]
    rls_kernel<<<BATCH, NTHREADS>>>(x_seq, d_seq, lambdas, y_out, w_out);
}

// round 10
// speedup vs baseline: 3.1828x; 1.7809x over previous
#include <cuda_runtime.h>
#include <cstdint>

#define BATCH 64
#define NSTEPS 2000
#define TAPS 64
#define NTHREADS 128
#define CHUNK 16
#define NCHUNK (NSTEPS / CHUNK)   // 125
#define SYM_CHUNKS 6              // symmetrize every 96 steps

using ull = unsigned long long;

__device__ __forceinline__ void cp16(uint32_t dst_smem, const void* src_gmem) {
    asm volatile("cp.async.cg.shared.global [%0], [%1], 16;\n"
                 :: "r"(dst_smem), "l"(src_gmem));
}
__device__ __forceinline__ void cp_commit() {
    asm volatile("cp.async.commit_group;\n");
}
template <int N>
__device__ __forceinline__ void cp_wait() {
    asm volatile("cp.async.wait_group %0;\n" :: "n"(N));
}

// ---- packed f32x2 ops (Blackwell sm_103a) ----
__device__ __forceinline__ ull ffma2(ull a, ull b, ull c) {
    ull d; asm("fma.rn.f32x2 %0, %1, %2, %3;" : "=l"(d) : "l"(a), "l"(b), "l"(c));
    return d;
}
__device__ __forceinline__ ull fadd2(ull a, ull b) {
    ull d; asm("add.rn.f32x2 %0, %1, %2;" : "=l"(d) : "l"(a), "l"(b));
    return d;
}
__device__ __forceinline__ ull pack2(float x) {
    ull d; uint32_t t = __float_as_uint(x);
    asm("mov.b64 %0, {%1, %2};" : "=l"(d) : "r"(t), "r"(t));
    return d;
}
__device__ __forceinline__ ull pack2two(float a, float b) {
    ull d;
    asm("mov.b64 %0, {%1, %2};" : "=l"(d)
        : "r"(__float_as_uint(a)), "r"(__float_as_uint(b)));
    return d;
}
__device__ __forceinline__ void unpack2(ull v, float& a, float& b) {
    uint32_t lo, hi;
    asm("mov.b64 {%0, %1}, %2;" : "=r"(lo), "=r"(hi) : "l"(v));
    a = __uint_as_float(lo); b = __uint_as_float(hi);
}
__device__ __forceinline__ float hadd2(ull v) {
    float a, b; unpack2(v, a, b); return a + b;
}

__global__ void __launch_bounds__(NTHREADS, 1)
rls_kernel(const float* __restrict__ x_seq,
           const float* __restrict__ d_seq,
           const float* __restrict__ lambdas,
           float* __restrict__ y_out,
           float* __restrict__ w_out)
{
    const int b   = blockIdx.x;
    const int tid = threadIdx.x;
    const int i   = tid >> 1;   // row 0..63
    const int c   = tid & 1;    // column-half 0/1

    __shared__ __align__(16) float xc[4][CHUNK][TAPS];   // rotating chunk bufs
    __shared__ __align__(16) float dc[4][CHUNK];
    __shared__ __align__(16) float lc[4][CHUNK];
    __shared__ __align__(16) float Uxbuf[2][TAPS];
    __shared__ float tile[TAPS][TAPS + 1];

    // packed state: 16 x f32x2 = this thread's 32-col half of each vector
    ull Q2[16];   // row i of Q (P = sigma * Q), cols [32c, 32c+32)
    ull w2[16];   // w half (redundant across rows)
    ull u2[16];   // u_t half
    ull x2[16];   // x_{t+1} half
#pragma unroll
    for (int k = 0; k < 16; k++) {
        const int j0 = c * 32 + 2 * k;
        Q2[k] = pack2two(i == j0 ? 1.0f : 0.0f, i == j0 + 1 ? 1.0f : 0.0f);
        w2[k] = 0ull;
    }
    float sigma = 1.0f, y = 0.0f, alpha, Uxi;

    const float* xb = x_seq + (size_t)b * NSTEPS * TAPS;
    const float* db = d_seq + (size_t)b * NSTEPS;

    const uint32_t xc_s = (uint32_t)__cvta_generic_to_shared(&xc[0][0][0]);
    const uint32_t dc_s = (uint32_t)__cvta_generic_to_shared(&dc[0][0]);
    const uint32_t lc_s = (uint32_t)__cvta_generic_to_shared(&lc[0][0]);

    auto issue_chunk = [&](int ck, int cb) {
#pragma unroll
        for (int j = 0; j < 2; j++)
            cp16(xc_s + (uint32_t)(cb * (CHUNK * TAPS) + j * 512) * 4 + tid * 16,
                 xb + (size_t)ck * CHUNK * TAPS + j * 512 + tid * 4);
        if (tid < 4)
            cp16(dc_s + (uint32_t)(cb * CHUNK) * 4 + tid * 16,
                 db + ck * CHUNK + tid * 4);
        else if (tid < 8)
            cp16(lc_s + (uint32_t)(cb * CHUNK) * 4 + (tid - 4) * 16,
                 lambdas + ck * CHUNK + (tid - 4) * 4);
        cp_commit();
    };

    issue_chunk(0, 0);
    issue_chunk(1, 1);
    cp_wait<1>();
    __syncthreads();

    // ---- bootstrap: u_0 = x_0 (Q = I), alpha_0 = x_0'x_0, y_0 = 0 ----
#pragma unroll
    for (int k = 0; k < 8; k++) {
        const ulonglong2 v = *(const ulonglong2*)(&xc[0][0][c * 32 + 4 * k]);
        x2[2 * k] = v.x; x2[2 * k + 1] = v.y;
    }
#pragma unroll
    for (int k = 0; k < 16; k++) u2[k] = x2[k];
    Uxi = xc[0][0][i];
    {
        ull a0 = 0ull, a1 = 0ull;
#pragma unroll
        for (int k = 0; k < 16; k += 2) {
            a0 = ffma2(x2[k], x2[k], a0);
            a1 = ffma2(x2[k + 1], x2[k + 1], a1);
        }
        float h = hadd2(fadd2(a0, a1));
        alpha = h + __shfl_xor_sync(0xffffffffu, h, 1);
    }
    float d_nxt = dc[0][0], lam_nxt = lc[0][0];

    for (int ck = 0; ck < NCHUNK; ck++) {
        if (ck + 2 < NCHUNK) { issue_chunk(ck + 2, (ck + 2) & 3); cp_wait<1>(); }
        else                 { cp_wait<0>(); }
        __syncthreads();

#pragma unroll 4
        for (int s = 0; s < CHUNK; s++) {
            const int t  = ck * CHUNK + s;
            const int wb = (t & 1) ^ 1;          // Uxbuf slot written this step

            // ---- step-t scalars ----
            const float d_r = d_nxt, lam_r = lam_nxt;
            const float lam   = fminf(fmaxf(lam_r, 1e-4f), 0.9999f);
            const float denom = fmaf(sigma, alpha, lam);
            const float kk    = sigma * __fdividef(1.0f, denom);
            const float e     = d_r - y;
            if (tid == 0) y_out[(size_t)b * NSTEPS + t] = y;
            const float ke = kk * e;
            sigma = sigma / lam;                 // exact div (error never damps)

            const int t1  = (t + 1 < NSTEPS) ? t + 1 : t;
            const int cb1 = (t1 >> 4) & 3, sl1 = t1 & (CHUNK - 1);
            d_nxt = dc[cb1][sl1]; lam_nxt = lc[cb1][sl1];

            // ---- w_{t+1} = w_t + ke * u_t ----
            const ull ke2 = pack2(ke);
#pragma unroll
            for (int k = 0; k < 16; k++) w2[k] = ffma2(ke2, u2[k], w2[k]);

            // ---- load x_{t+1} half ----
#pragma unroll
            for (int k = 0; k < 8; k++) {
                const ulonglong2 v = *(const ulonglong2*)(&xc[cb1][sl1][c * 32 + 4 * k]);
                x2[2 * k] = v.x; x2[2 * k + 1] = v.y;
            }

            // ---- matvec v = Q x1, gamma = u'x1, ynext = w'x1 (packed) ----
            ull m0 = 0ull, m1 = 0ull, m2 = 0ull, m3 = 0ull;
            ull g0 = 0ull, g1 = 0ull, y0 = 0ull, y1 = 0ull;
#pragma unroll
            for (int k = 0; k < 16; k += 4) {
                m0 = ffma2(Q2[k + 0], x2[k + 0], m0);
                m1 = ffma2(Q2[k + 1], x2[k + 1], m1);
                m2 = ffma2(Q2[k + 2], x2[k + 2], m2);
                m3 = ffma2(Q2[k + 3], x2[k + 3], m3);
                g0 = ffma2(u2[k + 0], x2[k + 0], g0);
                g1 = ffma2(u2[k + 1], x2[k + 1], g1);
                g0 = ffma2(u2[k + 2], x2[k + 2], g0);
                g1 = ffma2(u2[k + 3], x2[k + 3], g1);
                y0 = ffma2(w2[k + 0], x2[k + 0], y0);
                y1 = ffma2(w2[k + 1], x2[k + 1], y1);
                y0 = ffma2(w2[k + 2], x2[k + 2], y0);
                y1 = ffma2(w2[k + 3], x2[k + 3], y1);
            }
            float vpart = hadd2(fadd2(fadd2(m0, m1), fadd2(m2, m3)));
            const float Vxi = vpart + __shfl_xor_sync(0xffffffffu, vpart, 1);
            float gh = hadd2(fadd2(g0, g1));
            const float gam = gh + __shfl_xor_sync(0xffffffffu, gh, 1);
            float yh = hadd2(fadd2(y0, y1));
            y = yh + __shfl_xor_sync(0xffffffffu, yh, 1);   // y_{t+1}

            // ---- Q_{t+1} = Q_t - kk * u_t u_t'  (OLD Uxi) ----
            const ull mq = pack2(-kk * Uxi);
#pragma unroll
            for (int k = 0; k < 16; k++) Q2[k] = ffma2(mq, u2[k], Q2[k]);

            // ---- u_{t+1,i}; publish ----
            const float unew = fmaf(-kk * gam, Uxi, Vxi);
            if (c == 0) Uxbuf[wb][i] = unew;
            Uxi = unew;

            __syncthreads();   // the one per-step barrier

            // ---- post-barrier: u_{t+1} half; alpha_{t+1} = u_{t+1}'x_{t+1} ----
            ull a0 = 0ull, a1 = 0ull;
#pragma unroll
            for (int k = 0; k < 8; k++) {
                const ulonglong2 v = *(const ulonglong2*)(&Uxbuf[wb][c * 32 + 4 * k]);
                u2[2 * k] = v.x; u2[2 * k + 1] = v.y;
                a0 = ffma2(v.x, x2[2 * k], a0);
                a1 = ffma2(v.y, x2[2 * k + 1], a1);
            }
            float ah = hadd2(fadd2(a0, a1));
            alpha = ah + __shfl_xor_sync(0xffffffffu, ah, 1);
        }

        // ---- symmetrize every SYM_CHUNKS chunks (kills undamped antisym mode) ----
        if ((ck % SYM_CHUNKS) == (SYM_CHUNKS - 1)) {
#pragma unroll
            for (int k = 0; k < 16; k++) {
                float f0, f1; unpack2(Q2[k], f0, f1);
                tile[i][c * 32 + 2 * k]     = f0;
                tile[i][c * 32 + 2 * k + 1] = f1;
            }
            __syncthreads();
#pragma unroll
            for (int k = 0; k < 16; k++) {
                float f0, f1; unpack2(Q2[k], f0, f1);
                const float t0 = tile[c * 32 + 2 * k][i];
                const float t1 = tile[c * 32 + 2 * k + 1][i];
                Q2[k] = pack2two(0.5f * (f0 + t0), 0.5f * (f1 + t1));
            }
            __syncthreads();
        }
    }

    // ---- outputs: w (tid 0 writes half c=0, tid 1 writes half c=1) ----
    if (i == 0) {
#pragma unroll
        for (int k = 0; k < 16; k++) {
            float f0, f1; unpack2(w2[k], f0, f1);
            w_out[(size_t)b * TAPS + c * 32 + 2 * k]     = f0;
            w_out[(size_t)b * TAPS + c * 32 + 2 * k + 1] = f1;
        }
    }
}

extern "C" void kernel_launch(void* const* d_in, const int* in_sizes, int n_in,
                              void* d_out, int out_size)
{
    const float* x_seq   = (const float*)d_in[0];
    const float* d_seq   = (const float*)d_in[1];
    const float* lambdas = (const float*)d_in[2];
    float* y_out = (float*)d_out;                          // [64, 2000]
    float* w_out = (float*)d_out + (size_t)BATCH * NSTEPS; // [64, 64]
    rls_kernel<<<BATCH, NTHREADS>>>(x_seq, d_seq, lambdas, y_out, w_out);
}

// round 11
// speedup vs baseline: 3.1932x; 1.0033x over previous
#include <cuda_runtime.h>
#include <cstdint>

#define BATCH 64
#define NSTEPS 2000
#define TAPS 64
#define NTHREADS 128
#define CHUNK 16
#define NCHUNK (NSTEPS / CHUNK)   // 125
#define SYM_CHUNKS 6              // symmetrize every 96 steps

using ull = unsigned long long;

__device__ __forceinline__ void cp16(uint32_t dst_smem, const void* src_gmem) {
    asm volatile("cp.async.cg.shared.global [%0], [%1], 16;\n"
                 :: "r"(dst_smem), "l"(src_gmem));
}
__device__ __forceinline__ void cp_commit() {
    asm volatile("cp.async.commit_group;\n");
}
template <int N>
__device__ __forceinline__ void cp_wait() {
    asm volatile("cp.async.wait_group %0;\n" :: "n"(N));
}

// ---- packed f32x2 ops (Blackwell sm_103a) ----
__device__ __forceinline__ ull ffma2(ull a, ull b, ull c) {
    ull d; asm("fma.rn.f32x2 %0, %1, %2, %3;" : "=l"(d) : "l"(a), "l"(b), "l"(c));
    return d;
}
__device__ __forceinline__ ull fadd2(ull a, ull b) {
    ull d; asm("add.rn.f32x2 %0, %1, %2;" : "=l"(d) : "l"(a), "l"(b));
    return d;
}
__device__ __forceinline__ ull pack2(float x) {
    ull d; uint32_t t = __float_as_uint(x);
    asm("mov.b64 %0, {%1, %2};" : "=l"(d) : "r"(t), "r"(t));
    return d;
}
__device__ __forceinline__ ull pack2two(float a, float b) {
    ull d;
    asm("mov.b64 %0, {%1, %2};" : "=l"(d)
        : "r"(__float_as_uint(a)), "r"(__float_as_uint(b)));
    return d;
}
__device__ __forceinline__ void unpack2(ull v, float& a, float& b) {
    uint32_t lo, hi;
    asm("mov.b64 {%0, %1}, %2;" : "=r"(lo), "=r"(hi) : "l"(v));
    a = __uint_as_float(lo); b = __uint_as_float(hi);
}
__device__ __forceinline__ float hadd2(ull v) {
    float a, b; unpack2(v, a, b); return a + b;
}

__global__ void __launch_bounds__(NTHREADS, 1)
rls_kernel(const float* __restrict__ x_seq,
           const float* __restrict__ d_seq,
           const float* __restrict__ lambdas,
           float* __restrict__ y_out,
           float* __restrict__ w_out)
{
    const int b   = blockIdx.x;
    const int tid = threadIdx.x;
    const int i   = tid >> 1;   // row 0..63
    const int c   = tid & 1;    // column-half 0/1

    __shared__ __align__(16) float xc[4][CHUNK][TAPS];   // rotating chunk bufs
    __shared__ __align__(16) float dc[4][CHUNK];
    __shared__ __align__(16) float lc[4][CHUNK];
    __shared__ __align__(16) float Uxbuf[2][TAPS];
    __shared__ float tile[TAPS][TAPS + 1];

    // packed state: 16 x f32x2 = this thread's 32-col half of each vector
    ull Q2[16];   // row i of Q (P = sigma * Q), cols [32c, 32c+32)
    ull w2[16];   // w half (redundant across rows)
    ull u2[16];   // u_t half
    ull x2[16];   // x_{t+1} half (lookahead)
#pragma unroll
    for (int k = 0; k < 16; k++) {
        const int j0 = c * 32 + 2 * k;
        Q2[k] = pack2two(i == j0 ? 1.0f : 0.0f, i == j0 + 1 ? 1.0f : 0.0f);
        w2[k] = 0ull;
    }
    float sigma = 1.0f;
    float y     = 0.0f;    // y_t  (y_0 = 0)
    float delta = 0.0f;    // delta_{t-1} = w_t' x_t ... carried as w_t'x_{t+1}
    float Uxi, Vxi;

    const float* xb = x_seq + (size_t)b * NSTEPS * TAPS;
    const float* db = d_seq + (size_t)b * NSTEPS;

    const uint32_t xc_s = (uint32_t)__cvta_generic_to_shared(&xc[0][0][0]);
    const uint32_t dc_s = (uint32_t)__cvta_generic_to_shared(&dc[0][0]);
    const uint32_t lc_s = (uint32_t)__cvta_generic_to_shared(&lc[0][0]);

    auto issue_chunk = [&](int ck, int cb) {
#pragma unroll
        for (int j = 0; j < 2; j++)
            cp16(xc_s + (uint32_t)(cb * (CHUNK * TAPS) + j * 512) * 4 + tid * 16,
                 xb + (size_t)ck * CHUNK * TAPS + j * 512 + tid * 4);
        if (tid < 4)
            cp16(dc_s + (uint32_t)(cb * CHUNK) * 4 + tid * 16,
                 db + ck * CHUNK + tid * 4);
        else if (tid < 8)
            cp16(lc_s + (uint32_t)(cb * CHUNK) * 4 + (tid - 4) * 16,
                 lambdas + ck * CHUNK + (tid - 4) * 4);
        cp_commit();
    };

    issue_chunk(0, 0);
    issue_chunk(1, 1);
    cp_wait<1>();
    __syncthreads();

    // ---- bootstrap: u_0 = x_0 (Q = I); v_0 = Q_0 x_1 = x_1; x2 = x_1 ----
    Uxi = xc[0][0][i];            // u_0,i
    if (c == 0) Uxbuf[0][i] = Uxi;
    Vxi = xc[0][1][i];            // v_0,i = x_1,i
#pragma unroll
    for (int k = 0; k < 8; k++) {
        const ulonglong2 v = *(const ulonglong2*)(&xc[0][1][c * 32 + 4 * k]);
        x2[2 * k] = v.x; x2[2 * k + 1] = v.y;
    }
    float d_cur = dc[0][0], lam_cur = lc[0][0];

    for (int ck = 0; ck < NCHUNK; ck++) {
        if (ck + 2 < NCHUNK) { issue_chunk(ck + 2, (ck + 2) & 3); cp_wait<1>(); }
        else                 { cp_wait<0>(); }
        __syncthreads();
        const int cbt = ck & 3;

#pragma unroll 4
        for (int s = 0; s < CHUNK; s++) {
            const int t  = ck * CHUNK + s;
            const int rb = t & 1;               // Uxbuf slot with u_t

            // ---- post-barrier: load u_t (+ x_t from smem), dual dots ----
            //      gam_t = u_t'x_{t+1} (x2 regs), alpha_t = u_t'x_t (smem)
            ull g0 = 0ull, g1 = 0ull, a0 = 0ull, a1 = 0ull;
#pragma unroll
            for (int k = 0; k < 8; k++) {
                const ulonglong2 uu = *(const ulonglong2*)(&Uxbuf[rb][c * 32 + 4 * k]);
                const ulonglong2 xo = *(const ulonglong2*)(&xc[cbt][s][c * 32 + 4 * k]);
                u2[2 * k] = uu.x; u2[2 * k + 1] = uu.y;
                g0 = ffma2(uu.x, x2[2 * k],     g0);
                g1 = ffma2(uu.y, x2[2 * k + 1], g1);
                a0 = ffma2(uu.x, xo.x, a0);
                a1 = ffma2(uu.y, xo.y, a1);
            }
            float gh = hadd2(fadd2(g0, g1));
            float ah = hadd2(fadd2(a0, a1));
            const float gam   = gh + __shfl_xor_sync(0xffffffffu, gh, 1);
            const float alpha = ah + __shfl_xor_sync(0xffffffffu, ah, 1);

            // ---- scalars ----
            const float lam   = fminf(fmaxf(lam_cur, 1e-4f), 0.9999f);
            const float denom = fmaf(sigma, alpha, lam);
            const float kk    = sigma * __fdividef(1.0f, denom);
            const float e     = d_cur - y;
            if (tid == 0) y_out[(size_t)b * NSTEPS + t] = y;
            const float ke = kk * e;
            y = fmaf(ke, gam, delta);            // y_{t+1} = delta_t + ke*gam
            sigma = sigma / lam;                 // exact div (error never damps)

            // ---- publish u_{t+1} ASAP (gates the barrier) ----
            const float unew = fmaf(-kk * gam, Uxi, Vxi);
            if (c == 0) Uxbuf[rb ^ 1][i] = unew;

            // ---- Q_{t+1} = Q_t - kk u_t u_t' (old Uxi); w_{t+1} = w_t + ke u_t ----
            const ull mq  = pack2(-kk * Uxi);
            const ull ke2 = pack2(ke);
#pragma unroll
            for (int k = 0; k < 16; k++) {
                Q2[k] = ffma2(mq,  u2[k], Q2[k]);
                w2[k] = ffma2(ke2, u2[k], w2[k]);
            }
            Uxi = unew;

            // ---- prefetch next scalars ----
            const int t1 = (t + 1 < NSTEPS) ? t + 1 : t;
            d_cur  = dc[(t1 >> 4) & 3][t1 & (CHUNK - 1)];
            lam_cur = lc[(t1 >> 4) & 3][t1 & (CHUNK - 1)];

            // ---- tail: load x_{t+2}; v_{t+1} = Q_{t+1}x_{t+2}; delta_{t+1} ----
            const int t2  = (t + 2 < NSTEPS) ? t + 2 : NSTEPS - 1;
            const int cb2 = (t2 >> 4) & 3, sl2 = t2 & (CHUNK - 1);
            ull m0 = 0ull, m1 = 0ull, m2 = 0ull, m3 = 0ull;
            ull dd0 = 0ull, dd1 = 0ull;
#pragma unroll
            for (int k = 0; k < 8; k++) {
                const ulonglong2 v = *(const ulonglong2*)(&xc[cb2][sl2][c * 32 + 4 * k]);
                x2[2 * k] = v.x; x2[2 * k + 1] = v.y;
            }
#pragma unroll
            for (int k = 0; k < 16; k += 4) {
                m0  = ffma2(Q2[k + 0], x2[k + 0], m0);
                m1  = ffma2(Q2[k + 1], x2[k + 1], m1);
                m2  = ffma2(Q2[k + 2], x2[k + 2], m2);
                m3  = ffma2(Q2[k + 3], x2[k + 3], m3);
                dd0 = ffma2(w2[k + 0], x2[k + 0], dd0);
                dd1 = ffma2(w2[k + 1], x2[k + 1], dd1);
                dd0 = ffma2(w2[k + 2], x2[k + 2], dd0);
                dd1 = ffma2(w2[k + 3], x2[k + 3], dd1);
            }
            float vpart = hadd2(fadd2(fadd2(m0, m1), fadd2(m2, m3)));
            float dh    = hadd2(fadd2(dd0, dd1));
            Vxi   = vpart + __shfl_xor_sync(0xffffffffu, vpart, 1);
            delta = dh    + __shfl_xor_sync(0xffffffffu, dh, 1);

            __syncthreads();   // the one per-step barrier
        }

        // ---- symmetrize every SYM_CHUNKS chunks (kills undamped antisym mode) ----
        if ((ck % SYM_CHUNKS) == (SYM_CHUNKS - 1)) {
#pragma unroll
            for (int k = 0; k < 16; k++) {
                float f0, f1; unpack2(Q2[k], f0, f1);
                tile[i][c * 32 + 2 * k]     = f0;
                tile[i][c * 32 + 2 * k + 1] = f1;
            }
            __syncthreads();
#pragma unroll
            for (int k = 0; k < 16; k++) {
                float f0, f1; unpack2(Q2[k], f0, f1);
                const float t0 = tile[c * 32 + 2 * k][i];
                const float t1 = tile[c * 32 + 2 * k + 1][i];
                Q2[k] = pack2two(0.5f * (f0 + t0), 0.5f * (f1 + t1));
            }
            __syncthreads();
        }
    }

    // ---- outputs: w (tid 0 writes half c=0, tid 1 writes half c=1) ----
    if (i == 0) {
#pragma unroll
        for (int k = 0; k < 16; k++) {
            float f0, f1; unpack2(w2[k], f0, f1);
            w_out[(size_t)b * TAPS + c * 32 + 2 * k]     = f0;
            w_out[(size_t)b * TAPS + c * 32 + 2 * k + 1] = f1;
        }
    }
}

extern "C" void kernel_launch(void* const* d_in, const int* in_sizes, int n_in,
                              void* d_out, int out_size)
{
    const float* x_seq   = (const float*)d_in[0];
    const float* d_seq   = (const float*)d_in[1];
    const float* lambdas = (const float*)d_in[2];
    float* y_out = (float*)d_out;                          // [64, 2000]
    float* w_out = (float*)d_out + (size_t)BATCH * NSTEPS; // [64, 64]
    rls_kernel<<<BATCH, NTHREADS>>>(x_seq, d_seq, lambdas, y_out, w_out);
}